// round 2
// baseline (speedup 1.0000x reference)
#include <cuda_runtime.h>
#include <cuda_bf16.h>
#include <cstdint>

// ===================== helpers =====================

__device__ __forceinline__ uint32_t smem_u32(const void* p) {
    uint32_t a;
    asm("{ .reg .u64 t; cvta.to.shared.u64 t, %1; cvt.u32.u64 %0, t; }" : "=r"(a) : "l"(p));
    return a;
}

#define LDMATRIX_X4(r0, r1, r2, r3, addr) \
    asm volatile("ldmatrix.sync.aligned.m8n8.x4.shared.b16 {%0,%1,%2,%3}, [%4];" \
        : "=r"(r0), "=r"(r1), "=r"(r2), "=r"(r3) : "r"(addr))

#define MMA16816(c, a0, a1, a2, a3, b0, b1) \
    asm volatile("mma.sync.aligned.m16n8k16.row.col.f32.bf16.bf16.f32 " \
        "{%0,%1,%2,%3}, {%4,%5,%6,%7}, {%8,%9}, {%0,%1,%2,%3};" \
        : "+f"((c)[0]), "+f"((c)[1]), "+f"((c)[2]), "+f"((c)[3]) \
        : "r"(a0), "r"(a1), "r"(a2), "r"(a3), "r"(b0), "r"(b1))

// ===================== Problem constants =====================

#define NN      16384
#define NFEAT   256
#define NHID    64
#define KC      64           // K chunk per pipeline step
#define NCHUNK  (NN / KC)    // 256
#define MTILE   128
#define NCTA1   (NN / MTILE) // 128

// Scratch (static device globals — allocation-free)
__device__ __align__(16) unsigned char g_Bh[NCHUNK * 8192];   // pre-swizzled bf16 hi tiles [chunk][64n x 64k]
__device__ __align__(16) unsigned char g_Bl[NCHUNK * 8192];   // bf16 lo tiles
__device__ __align__(16) float g_G[NN * 2];                   // h1 @ W2 (before +b2)
__device__ __align__(16) float g_pmax[NCTA1 * 2];             // per-CTA column maxes

// ===================== K1: B = x @ W1, split to bf16 hi/lo, pre-swizzled =====================
// grid 256, block 256, dyn smem = 64KB (W1) + 16KB (tiles)

__global__ __launch_bounds__(256) void k1_xw1(const float* __restrict__ x, const float* __restrict__ W1) {
    extern __shared__ char sm1[];
    float* W1s = (float*)sm1;                        // 65536 B
    unsigned char* bh = (unsigned char*)sm1 + 65536; // 8192 B
    unsigned char* bl = bh + 8192;

    int tid = threadIdx.x, wid = tid >> 5, lid = tid & 31;

    const float4* w4 = (const float4*)W1;
    float4* w4s = (float4*)W1s;
#pragma unroll
    for (int i = 0; i < 16; i++) w4s[tid + i * 256] = w4[tid + i * 256];
    __syncthreads();

    int b = blockIdx.x;   // chunk index; covers global k rows [64b, 64b+64)
    for (int i = 0; i < 8; i++) {
        int kl = wid * 8 + i;                 // local k row 0..63
        long k = (long)b * 64 + kl;
        const float* xr = x + k * 256;
        float a0 = 0.f, a1 = 0.f;             // n = 2*lid, 2*lid+1
#pragma unroll 8
        for (int j = 0; j < 256; j++) {
            float xv = __ldg(xr + j);
            float2 wv = *(const float2*)(W1s + j * 64 + 2 * lid);
            a0 = fmaf(xv, wv.x, a0);
            a1 = fmaf(xv, wv.y, a1);
        }
        // split-store: tile row = n, col = kl, SW128 swizzled image
#pragma unroll
        for (int t = 0; t < 2; t++) {
            float a = t ? a1 : a0;
            int n = 2 * lid + t;
            unsigned off = n * 128 + kl * 2;
            unsigned sw = off ^ ((off >> 3) & 0x70);
            __nv_bfloat16 h = __float2bfloat16(a);
            __nv_bfloat16 l = __float2bfloat16(a - __bfloat162float(h));
            *(__nv_bfloat16*)(bh + sw) = h;
            *(__nv_bfloat16*)(bl + sw) = l;
        }
    }
    __syncthreads();

    int4* gh = (int4*)g_Bh + (size_t)b * 512;
    int4* gl = (int4*)g_Bl + (size_t)b * 512;
    const int4* sh = (const int4*)bh;
    const int4* sl = (const int4*)bl;
#pragma unroll
    for (int i = 0; i < 2; i++) {
        gh[tid + i * 256] = sh[tid + i * 256];
        gl[tid + i * 256] = sl[tid + i * 256];
    }
}

// ===================== K2: pass 1 — H1 = relu(adj@B + b1); G = H1@W2 =====================
// grid 128, block 256 (8 warps, each owns 16 output rows x 64 cols, fp32 reg accum).
// Double-buffered: fp32 adj chunk -> bf16 hi/lo (swizzled smem) -> mma.sync m16n8k16,
// 3-term Markidis split (Ah*Bh + Al*Bh + Ah*Bl).

__global__ __launch_bounds__(256, 1) void k2_pass1(const float* __restrict__ adj,
                                                   const float* __restrict__ b1,
                                                   const float* __restrict__ W2) {
    extern __shared__ char sm2raw[];
    __shared__ float sW2[128];
    __shared__ float sb1[64];

    uint32_t raw = smem_u32(sm2raw);
    uint32_t pad = (1024u - (raw & 1023u)) & 1023u;
    char* sm = sm2raw + pad;
    uint32_t smb = raw + pad;

    // per-buffer layout (48KB): AH 0, AL 16384, BH 32768, BL 40960
    const int BUFSZ = 49152;

    int tid = threadIdx.x, wid = tid >> 5, lane = tid & 31;

    if (tid < 128) sW2[tid] = W2[tid];
    if (tid < 64)  sb1[tid] = b1[tid];

    float acc[8][4];
#pragma unroll
    for (int i = 0; i < 8; i++)
#pragma unroll
        for (int j = 0; j < 4; j++) acc[i][j] = 0.f;

    int rb = blockIdx.x * MTILE;

    // lane-derived ldmatrix addressing
    int rloc = lane & 15;
    uint32_t aRow = (uint32_t)((wid * 16 + rloc) * 128);
    uint32_t aHi  = (uint32_t)(lane >> 4);
    uint32_t aRx  = (uint32_t)(rloc & 7);
    int nloc = (lane & 7) + ((lane >> 4) << 3);
    uint32_t bKh = (uint32_t)((lane >> 3) & 1);
    uint32_t bNx = (uint32_t)(lane & 7);
    uint32_t bRow = (uint32_t)(nloc * 128);

    float4 v[8];
    int4 bh0, bh1, bl0, bl1;

    auto issue_loads = [&](int it) {
#pragma unroll
        for (int q = 0; q < 8; q++) {
            int li = q * 256 + tid;
            int row = li >> 4, qk = li & 15;     // 16 float4 per 64-float row
            v[q] = __ldg((const float4*)(adj + (long)(rb + row) * NN + (long)it * KC) + qk);
        }
        const int4* gbh = (const int4*)g_Bh + (size_t)it * 512;
        const int4* gbl = (const int4*)g_Bl + (size_t)it * 512;
        bh0 = __ldg(gbh + tid); bh1 = __ldg(gbh + tid + 256);
        bl0 = __ldg(gbl + tid); bl1 = __ldg(gbl + tid + 256);
    };

    auto store_chunk = [&](char* buf) {
#pragma unroll
        for (int q = 0; q < 8; q++) {
            int li = q * 256 + tid;
            int row = li >> 4, qk = li & 15;
            unsigned off = row * 128 + qk * 8;
            unsigned sw = off ^ ((row & 7) << 4);
            uint32_t h01, h23, l01, l23;
            asm("cvt.rn.bf16x2.f32 %0, %1, %2;" : "=r"(h01) : "f"(v[q].y), "f"(v[q].x));
            asm("cvt.rn.bf16x2.f32 %0, %1, %2;" : "=r"(h23) : "f"(v[q].w), "f"(v[q].z));
            float lx = v[q].x - __uint_as_float(h01 << 16);
            float ly = v[q].y - __uint_as_float(h01 & 0xffff0000u);
            float lz = v[q].z - __uint_as_float(h23 << 16);
            float lw = v[q].w - __uint_as_float(h23 & 0xffff0000u);
            asm("cvt.rn.bf16x2.f32 %0, %1, %2;" : "=r"(l01) : "f"(ly), "f"(lx));
            asm("cvt.rn.bf16x2.f32 %0, %1, %2;" : "=r"(l23) : "f"(lw), "f"(lz));
            *(uint2*)(buf + 0     + sw) = make_uint2(h01, h23);
            *(uint2*)(buf + 16384 + sw) = make_uint2(l01, l23);
        }
        ((int4*)(buf + 32768))[tid] = bh0; ((int4*)(buf + 32768))[tid + 256] = bh1;
        ((int4*)(buf + 40960))[tid] = bl0; ((int4*)(buf + 40960))[tid + 256] = bl1;
    };

    auto compute = [&](uint32_t bufaddr) {
        uint32_t AH_ = bufaddr, AL_ = bufaddr + 16384;
        uint32_t BH_ = bufaddr + 32768, BL_ = bufaddr + 40960;
#pragma unroll
        for (int ks = 0; ks < 4; ks++) {
            uint32_t au = ((((uint32_t)(ks * 2)) + aHi) ^ aRx) << 4;
            uint32_t ah[4], al[4];
            LDMATRIX_X4(ah[0], ah[1], ah[2], ah[3], AH_ + aRow + au);
            LDMATRIX_X4(al[0], al[1], al[2], al[3], AL_ + aRow + au);
            uint32_t bu = ((((uint32_t)(ks * 2)) + bKh) ^ bNx) << 4;
#pragma unroll
            for (int ntp = 0; ntp < 4; ntp++) {
                uint32_t bh[4], bl[4];
                LDMATRIX_X4(bh[0], bh[1], bh[2], bh[3], BH_ + bRow + bu + ntp * 2048);
                LDMATRIX_X4(bl[0], bl[1], bl[2], bl[3], BL_ + bRow + bu + ntp * 2048);
                MMA16816(acc[2 * ntp],     ah[0], ah[1], ah[2], ah[3], bh[0], bh[1]);
                MMA16816(acc[2 * ntp],     al[0], al[1], al[2], al[3], bh[0], bh[1]);
                MMA16816(acc[2 * ntp],     ah[0], ah[1], ah[2], ah[3], bl[0], bl[1]);
                MMA16816(acc[2 * ntp + 1], ah[0], ah[1], ah[2], ah[3], bh[2], bh[3]);
                MMA16816(acc[2 * ntp + 1], al[0], al[1], al[2], al[3], bh[2], bh[3]);
                MMA16816(acc[2 * ntp + 1], ah[0], ah[1], ah[2], ah[3], bl[2], bl[3]);
            }
        }
    };

    // prologue: chunk 0
    issue_loads(0);
    store_chunk(sm);
    __syncthreads();

    for (int it = 0; it < NCHUNK - 1; it++) {
        int s = it & 1;
        issue_loads(it + 1);
        compute(smb + s * BUFSZ);
        store_chunk(sm + (s ^ 1) * BUFSZ);
        __syncthreads();
    }
    compute(smb + ((NCHUNK - 1) & 1) * BUFSZ);

    // epilogue: relu(+b1) then @W2, reduce the 64-wide dot across the 4 lanes of each row group
    int t2 = 2 * (lane & 3);
    float g0a = 0.f, g1a = 0.f, g0b = 0.f, g1b = 0.f;
#pragma unroll
    for (int nt = 0; nt < 8; nt++) {
        int n0 = nt * 8 + t2;
        float h;
        h = fmaxf(acc[nt][0] + sb1[n0], 0.f);
        g0a = fmaf(h, sW2[2 * n0], g0a);     g1a = fmaf(h, sW2[2 * n0 + 1], g1a);
        h = fmaxf(acc[nt][1] + sb1[n0 + 1], 0.f);
        g0a = fmaf(h, sW2[2 * n0 + 2], g0a); g1a = fmaf(h, sW2[2 * n0 + 3], g1a);
        h = fmaxf(acc[nt][2] + sb1[n0], 0.f);
        g0b = fmaf(h, sW2[2 * n0], g0b);     g1b = fmaf(h, sW2[2 * n0 + 1], g1b);
        h = fmaxf(acc[nt][3] + sb1[n0 + 1], 0.f);
        g0b = fmaf(h, sW2[2 * n0 + 2], g0b); g1b = fmaf(h, sW2[2 * n0 + 3], g1b);
    }
#pragma unroll
    for (int o = 1; o <= 2; o <<= 1) {
        g0a += __shfl_xor_sync(0xFFFFFFFFu, g0a, o);
        g1a += __shfl_xor_sync(0xFFFFFFFFu, g1a, o);
        g0b += __shfl_xor_sync(0xFFFFFFFFu, g0b, o);
        g1b += __shfl_xor_sync(0xFFFFFFFFu, g1b, o);
    }
    if ((lane & 3) == 0) {
        int row = rb + wid * 16 + (lane >> 2);
        ((float2*)g_G)[row]     = make_float2(g0a, g1a);
        ((float2*)g_G)[row + 8] = make_float2(g0b, g1b);
    }
}

// ===================== K3: pass 2 — H2 = adj @ G, per-CTA max reduce =====================
// grid 128 CTAs (128 rows each), block 256, G (128KB) staged in smem.

__global__ __launch_bounds__(256) void k3_pass2(const float* __restrict__ adj) {
    extern __shared__ char sm3[];
    float4* gs4 = (float4*)sm3;  // 8192 float4 = G as float2[16384]
    __shared__ float red[16];

    int tid = threadIdx.x, wid = tid >> 5, lid = tid & 31;

    const float4* gg = (const float4*)g_G;
#pragma unroll
    for (int i = 0; i < 32; i++) gs4[tid + i * 256] = gg[tid + i * 256];
    __syncthreads();

    float m0 = -3.402823466e38f, m1 = -3.402823466e38f;
    int rbase = blockIdx.x * 128 + wid * 16;

    for (int r = 0; r < 16; r++) {
        const float4* arow = (const float4*)(adj + (long)(rbase + r) * NN);
        float a0 = 0.f, a1 = 0.f;
#pragma unroll 8
        for (int itj = 0; itj < 128; itj++) {
            int j4 = itj * 32 + lid;
            float4 av = __ldg(arow + j4);
            float4 ga = gs4[2 * j4];
            float4 gb = gs4[2 * j4 + 1];
            a0 = fmaf(av.x, ga.x, a0); a1 = fmaf(av.x, ga.y, a1);
            a0 = fmaf(av.y, ga.z, a0); a1 = fmaf(av.y, ga.w, a1);
            a0 = fmaf(av.z, gb.x, a0); a1 = fmaf(av.z, gb.y, a1);
            a0 = fmaf(av.w, gb.z, a0); a1 = fmaf(av.w, gb.w, a1);
        }
#pragma unroll
        for (int o = 16; o; o >>= 1) {
            a0 += __shfl_xor_sync(0xFFFFFFFFu, a0, o);
            a1 += __shfl_xor_sync(0xFFFFFFFFu, a1, o);
        }
        m0 = fmaxf(m0, a0);
        m1 = fmaxf(m1, a1);
    }
    if (lid == 0) { red[wid * 2] = m0; red[wid * 2 + 1] = m1; }
    __syncthreads();
    if (tid == 0) {
        float M0 = red[0], M1 = red[1];
#pragma unroll
        for (int w = 1; w < 8; w++) { M0 = fmaxf(M0, red[2 * w]); M1 = fmaxf(M1, red[2 * w + 1]); }
        g_pmax[blockIdx.x * 2] = M0;
        g_pmax[blockIdx.x * 2 + 1] = M1;
    }
}

// ===================== K4: final max reduce + Linear(2 -> 1) =====================

__global__ void k4_final(const float* __restrict__ W3, const float* __restrict__ b2,
                         const float* __restrict__ b3, float* __restrict__ out) {
    __shared__ float r[8];
    int tid = threadIdx.x;   // 128
    float m0 = g_pmax[tid * 2], m1 = g_pmax[tid * 2 + 1];
#pragma unroll
    for (int o = 16; o; o >>= 1) {
        m0 = fmaxf(m0, __shfl_xor_sync(0xFFFFFFFFu, m0, o));
        m1 = fmaxf(m1, __shfl_xor_sync(0xFFFFFFFFu, m1, o));
    }
    if ((tid & 31) == 0) { r[(tid >> 5) * 2] = m0; r[(tid >> 5) * 2 + 1] = m1; }
    __syncthreads();
    if (tid == 0) {
        float M0 = r[0], M1 = r[1];
#pragma unroll
        for (int w = 1; w < 4; w++) { M0 = fmaxf(M0, r[2 * w]); M1 = fmaxf(M1, r[2 * w + 1]); }
        M0 += b2[0];
        M1 += b2[1];
        out[0] = fmaf(M0, W3[0], fmaf(M1, W3[1], b3[0]));
    }
}

// ===================== Launch =====================

extern "C" void kernel_launch(void* const* d_in, const int* in_sizes, int n_in,
                              void* d_out, int out_size) {
    const float* x   = (const float*)d_in[0];
    const float* adj = (const float*)d_in[1];
    const float* W1  = (const float*)d_in[2];
    const float* b1  = (const float*)d_in[3];
    const float* W2  = (const float*)d_in[4];
    const float* b2  = (const float*)d_in[5];
    const float* W3  = (const float*)d_in[6];
    const float* b3  = (const float*)d_in[7];
    float* out = (float*)d_out;

    cudaFuncSetAttribute(k1_xw1,   cudaFuncAttributeMaxDynamicSharedMemorySize, 81920);
    cudaFuncSetAttribute(k2_pass1, cudaFuncAttributeMaxDynamicSharedMemorySize, 99328);
    cudaFuncSetAttribute(k3_pass2, cudaFuncAttributeMaxDynamicSharedMemorySize, 131072);

    k1_xw1<<<256, 256, 81920>>>(x, W1);
    k2_pass1<<<NCTA1, 256, 99328>>>(adj, b1, W2);
    k3_pass2<<<128, 256, 131072>>>(adj);
    k4_final<<<1, 128>>>(W3, b2, b3, out);
}

// round 3
// speedup vs baseline: 1.0148x; 1.0148x over previous
#include <cuda_runtime.h>
#include <cuda_bf16.h>
#include <cstdint>

// ===================== helpers =====================

__device__ __forceinline__ uint32_t smem_u32(const void* p) {
    uint32_t a;
    asm("{ .reg .u64 t; cvta.to.shared.u64 t, %1; cvt.u32.u64 %0, t; }" : "=r"(a) : "l"(p));
    return a;
}

#define LDMATRIX_X4(r0, r1, r2, r3, addr) \
    asm volatile("ldmatrix.sync.aligned.m8n8.x4.shared.b16 {%0,%1,%2,%3}, [%4];" \
        : "=r"(r0), "=r"(r1), "=r"(r2), "=r"(r3) : "r"(addr))

#define MMA16816(c, a0, a1, a2, a3, b0, b1) \
    asm volatile("mma.sync.aligned.m16n8k16.row.col.f32.bf16.bf16.f32 " \
        "{%0,%1,%2,%3}, {%4,%5,%6,%7}, {%8,%9}, {%0,%1,%2,%3};" \
        : "+f"((c)[0]), "+f"((c)[1]), "+f"((c)[2]), "+f"((c)[3]) \
        : "r"(a0), "r"(a1), "r"(a2), "r"(a3), "r"(b0), "r"(b1))

// ===================== Problem constants =====================

#define NN      16384
#define NFEAT   256
#define NHID    64
#define KC      64            // K chunk per pipeline step
#define NCHUNK  (NN / KC)     // 256
#define KSPLIT  2
#define NCH_H   (NCHUNK / KSPLIT)  // 128 chunks per CTA
#define MTILE   128
#define NMT     (NN / MTILE)  // 128 M-tiles

// Scratch (static device globals — allocation-free)
__device__ __align__(16) unsigned char g_Bh[NCHUNK * 8192];   // pre-swizzled bf16 hi tiles [chunk][64n x 64k]
__device__ __align__(16) unsigned char g_Bl[NCHUNK * 8192];   // bf16 lo tiles
__device__ __align__(16) float g_Hpart[KSPLIT * NN * NHID];   // partial pre-activation sums (8MB)
__device__ __align__(16) float g_G[NN * 2];                   // h1 @ W2 (before +b2)
__device__ __align__(16) float g_pmax[NMT * 2];               // per-CTA column maxes

// ===================== K1: B = x @ W1, split to bf16 hi/lo, pre-swizzled =====================

__global__ __launch_bounds__(256) void k1_xw1(const float* __restrict__ x, const float* __restrict__ W1) {
    extern __shared__ char sm1[];
    float* W1s = (float*)sm1;                        // 65536 B
    unsigned char* bh = (unsigned char*)sm1 + 65536; // 8192 B
    unsigned char* bl = bh + 8192;

    int tid = threadIdx.x, wid = tid >> 5, lid = tid & 31;

    const float4* w4 = (const float4*)W1;
    float4* w4s = (float4*)W1s;
#pragma unroll
    for (int i = 0; i < 16; i++) w4s[tid + i * 256] = w4[tid + i * 256];
    __syncthreads();

    int b = blockIdx.x;   // chunk index; covers global k rows [64b, 64b+64)
    for (int i = 0; i < 8; i++) {
        int kl = wid * 8 + i;                 // local k row 0..63
        long k = (long)b * 64 + kl;
        const float* xr = x + k * 256;
        float a0 = 0.f, a1 = 0.f;             // n = 2*lid, 2*lid+1
#pragma unroll 8
        for (int j = 0; j < 256; j++) {
            float xv = __ldg(xr + j);
            float2 wv = *(const float2*)(W1s + j * 64 + 2 * lid);
            a0 = fmaf(xv, wv.x, a0);
            a1 = fmaf(xv, wv.y, a1);
        }
#pragma unroll
        for (int t = 0; t < 2; t++) {
            float a = t ? a1 : a0;
            int n = 2 * lid + t;
            unsigned off = n * 128 + kl * 2;
            unsigned sw = off ^ ((off >> 3) & 0x70);
            __nv_bfloat16 h = __float2bfloat16(a);
            __nv_bfloat16 l = __float2bfloat16(a - __bfloat162float(h));
            *(__nv_bfloat16*)(bh + sw) = h;
            *(__nv_bfloat16*)(bl + sw) = l;
        }
    }
    __syncthreads();

    int4* gh = (int4*)g_Bh + (size_t)b * 512;
    int4* gl = (int4*)g_Bl + (size_t)b * 512;
    const int4* sh = (const int4*)bh;
    const int4* sl = (const int4*)bl;
#pragma unroll
    for (int i = 0; i < 2; i++) {
        gh[tid + i * 256] = sh[tid + i * 256];
        gl[tid + i * 256] = sl[tid + i * 256];
    }
}

// ===================== K2: pass 1 partial — Hpart[half] = adj[:, Khalf] @ B[Khalf] =====================
// grid 256 (= 128 M-tiles x 2 K-halves), block 256, 2 CTAs/SM.
// Double-buffered: fp32 adj chunk -> bf16 hi/lo (swizzled smem) -> mma.sync m16n8k16,
// 3-term Markidis split (Ah*Bh + Al*Bh + Ah*Bl), fp32 register accumulators.

__global__ __launch_bounds__(256, 2) void k2_pass1(const float* __restrict__ adj) {
    extern __shared__ char sm2raw[];
    uint32_t raw = smem_u32(sm2raw);
    uint32_t pad = (1024u - (raw & 1023u)) & 1023u;
    char* sm = sm2raw + pad;
    uint32_t smb = raw + pad;

    // per-buffer layout (48KB): AH 0, AL 16384, BH 32768, BL 40960
    const int BUFSZ = 49152;

    int tid = threadIdx.x, wid = tid >> 5, lane = tid & 31;

    int mt   = blockIdx.x >> 1;        // M-tile 0..127
    int half = blockIdx.x & 1;         // K half
    int rb = mt * MTILE;
    int c0 = half * NCH_H;

    float acc[8][4];
#pragma unroll
    for (int i = 0; i < 8; i++)
#pragma unroll
        for (int j = 0; j < 4; j++) acc[i][j] = 0.f;

    // lane-derived ldmatrix addressing
    int rloc = lane & 15;
    uint32_t aRow = (uint32_t)((wid * 16 + rloc) * 128);
    uint32_t aHi  = (uint32_t)(lane >> 4);
    uint32_t aRx  = (uint32_t)(rloc & 7);
    int nloc = (lane & 7) + ((lane >> 4) << 3);
    uint32_t bKh = (uint32_t)((lane >> 3) & 1);
    uint32_t bNx = (uint32_t)(lane & 7);
    uint32_t bRow = (uint32_t)(nloc * 128);

    float4 v[8];
    int4 bh0, bh1, bl0, bl1;

    auto issue_loads = [&](int ci) {
#pragma unroll
        for (int q = 0; q < 8; q++) {
            int li = q * 256 + tid;
            int row = li >> 4, qk = li & 15;     // 16 float4 per 64-float row
            v[q] = __ldg((const float4*)(adj + (long)(rb + row) * NN + (long)ci * KC) + qk);
        }
        const int4* gbh = (const int4*)g_Bh + (size_t)ci * 512;
        const int4* gbl = (const int4*)g_Bl + (size_t)ci * 512;
        bh0 = __ldg(gbh + tid); bh1 = __ldg(gbh + tid + 256);
        bl0 = __ldg(gbl + tid); bl1 = __ldg(gbl + tid + 256);
    };

    auto store_chunk = [&](char* buf) {
#pragma unroll
        for (int q = 0; q < 8; q++) {
            int li = q * 256 + tid;
            int row = li >> 4, qk = li & 15;
            unsigned off = row * 128 + qk * 8;
            unsigned sw = off ^ ((row & 7) << 4);
            uint32_t h01, h23, l01, l23;
            asm("cvt.rn.bf16x2.f32 %0, %1, %2;" : "=r"(h01) : "f"(v[q].y), "f"(v[q].x));
            asm("cvt.rn.bf16x2.f32 %0, %1, %2;" : "=r"(h23) : "f"(v[q].w), "f"(v[q].z));
            float lx = v[q].x - __uint_as_float(h01 << 16);
            float ly = v[q].y - __uint_as_float(h01 & 0xffff0000u);
            float lz = v[q].z - __uint_as_float(h23 << 16);
            float lw = v[q].w - __uint_as_float(h23 & 0xffff0000u);
            asm("cvt.rn.bf16x2.f32 %0, %1, %2;" : "=r"(l01) : "f"(ly), "f"(lx));
            asm("cvt.rn.bf16x2.f32 %0, %1, %2;" : "=r"(l23) : "f"(lw), "f"(lz));
            *(uint2*)(buf + 0     + sw) = make_uint2(h01, h23);
            *(uint2*)(buf + 16384 + sw) = make_uint2(l01, l23);
        }
        ((int4*)(buf + 32768))[tid] = bh0; ((int4*)(buf + 32768))[tid + 256] = bh1;
        ((int4*)(buf + 40960))[tid] = bl0; ((int4*)(buf + 40960))[tid + 256] = bl1;
    };

    auto compute = [&](uint32_t bufaddr) {
        uint32_t AH_ = bufaddr, AL_ = bufaddr + 16384;
        uint32_t BH_ = bufaddr + 32768, BL_ = bufaddr + 40960;
#pragma unroll
        for (int ks = 0; ks < 4; ks++) {
            uint32_t au = ((((uint32_t)(ks * 2)) + aHi) ^ aRx) << 4;
            uint32_t ah[4], al[4];
            LDMATRIX_X4(ah[0], ah[1], ah[2], ah[3], AH_ + aRow + au);
            LDMATRIX_X4(al[0], al[1], al[2], al[3], AL_ + aRow + au);
            uint32_t bu = ((((uint32_t)(ks * 2)) + bKh) ^ bNx) << 4;
#pragma unroll
            for (int ntp = 0; ntp < 4; ntp++) {
                uint32_t bh[4], bl[4];
                LDMATRIX_X4(bh[0], bh[1], bh[2], bh[3], BH_ + bRow + bu + ntp * 2048);
                LDMATRIX_X4(bl[0], bl[1], bl[2], bl[3], BL_ + bRow + bu + ntp * 2048);
                MMA16816(acc[2 * ntp],     ah[0], ah[1], ah[2], ah[3], bh[0], bh[1]);
                MMA16816(acc[2 * ntp],     al[0], al[1], al[2], al[3], bh[0], bh[1]);
                MMA16816(acc[2 * ntp],     ah[0], ah[1], ah[2], ah[3], bl[0], bl[1]);
                MMA16816(acc[2 * ntp + 1], ah[0], ah[1], ah[2], ah[3], bh[2], bh[3]);
                MMA16816(acc[2 * ntp + 1], al[0], al[1], al[2], al[3], bh[2], bh[3]);
                MMA16816(acc[2 * ntp + 1], ah[0], ah[1], ah[2], ah[3], bl[2], bl[3]);
            }
        }
    };

    // prologue: first chunk of this half
    issue_loads(c0);
    store_chunk(sm);
    __syncthreads();

    for (int it = 0; it < NCH_H - 1; it++) {
        int s = it & 1;
        issue_loads(c0 + it + 1);
        compute(smb + s * BUFSZ);
        store_chunk(sm + (s ^ 1) * BUFSZ);
        __syncthreads();
    }
    compute(smb + ((NCH_H - 1) & 1) * BUFSZ);

    // epilogue: write raw partial sums (fragment -> [row][n], coalesced float2)
    float* hp = g_Hpart + (size_t)half * NN * NHID;
    int r0 = rb + wid * 16 + (lane >> 2);
    int ncol = 2 * (lane & 3);
#pragma unroll
    for (int nt = 0; nt < 8; nt++) {
        *(float2*)(hp + (size_t)r0 * NHID + nt * 8 + ncol)       = make_float2(acc[nt][0], acc[nt][1]);
        *(float2*)(hp + (size_t)(r0 + 8) * NHID + nt * 8 + ncol) = make_float2(acc[nt][2], acc[nt][3]);
    }
}

// ===================== K2b: combine halves, +b1, relu, @W2 -> g_G =====================
// grid 64, block 256: one thread per node row.

__global__ __launch_bounds__(256) void k2b_combine(const float* __restrict__ b1,
                                                   const float* __restrict__ W2) {
    __shared__ float sb1[64];
    __shared__ float sW2[128];
    int tid = threadIdx.x;
    if (tid < 64)  sb1[tid] = b1[tid];
    if (tid >= 128 && tid < 256) sW2[tid - 128] = W2[tid - 128];
    __syncthreads();

    int row = blockIdx.x * 256 + tid;
    const float4* p0 = (const float4*)(g_Hpart) + (size_t)row * 16;
    const float4* p1 = (const float4*)(g_Hpart + (size_t)NN * NHID) + (size_t)row * 16;
    float g0 = 0.f, g1 = 0.f;
#pragma unroll
    for (int i = 0; i < 16; i++) {
        float4 a = __ldg(p0 + i);
        float4 b = __ldg(p1 + i);
        int n = i * 4;
        float h;
        h = fmaxf(a.x + b.x + sb1[n + 0], 0.f); g0 = fmaf(h, sW2[2*n + 0], g0); g1 = fmaf(h, sW2[2*n + 1], g1);
        h = fmaxf(a.y + b.y + sb1[n + 1], 0.f); g0 = fmaf(h, sW2[2*n + 2], g0); g1 = fmaf(h, sW2[2*n + 3], g1);
        h = fmaxf(a.z + b.z + sb1[n + 2], 0.f); g0 = fmaf(h, sW2[2*n + 4], g0); g1 = fmaf(h, sW2[2*n + 5], g1);
        h = fmaxf(a.w + b.w + sb1[n + 3], 0.f); g0 = fmaf(h, sW2[2*n + 6], g0); g1 = fmaf(h, sW2[2*n + 7], g1);
    }
    ((float2*)g_G)[row] = make_float2(g0, g1);
}

// ===================== K3: pass 2 — H2 = adj @ G, per-CTA max reduce =====================
// grid 128 CTAs (128 rows each), block 256, G (128KB) staged in smem.

__global__ __launch_bounds__(256) void k3_pass2(const float* __restrict__ adj) {
    extern __shared__ char sm3[];
    float4* gs4 = (float4*)sm3;  // 8192 float4 = G as float2[16384]
    __shared__ float red[16];

    int tid = threadIdx.x, wid = tid >> 5, lid = tid & 31;

    const float4* gg = (const float4*)g_G;
#pragma unroll
    for (int i = 0; i < 32; i++) gs4[tid + i * 256] = gg[tid + i * 256];
    __syncthreads();

    float m0 = -3.402823466e38f, m1 = -3.402823466e38f;
    int rbase = blockIdx.x * 128 + wid * 16;

    for (int r = 0; r < 16; r++) {
        const float4* arow = (const float4*)(adj + (long)(rbase + r) * NN);
        float a0 = 0.f, a1 = 0.f;
#pragma unroll 8
        for (int itj = 0; itj < 128; itj++) {
            int j4 = itj * 32 + lid;
            float4 av = __ldg(arow + j4);
            float4 ga = gs4[2 * j4];
            float4 gb = gs4[2 * j4 + 1];
            a0 = fmaf(av.x, ga.x, a0); a1 = fmaf(av.x, ga.y, a1);
            a0 = fmaf(av.y, ga.z, a0); a1 = fmaf(av.y, ga.w, a1);
            a0 = fmaf(av.z, gb.x, a0); a1 = fmaf(av.z, gb.y, a1);
            a0 = fmaf(av.w, gb.z, a0); a1 = fmaf(av.w, gb.w, a1);
        }
#pragma unroll
        for (int o = 16; o; o >>= 1) {
            a0 += __shfl_xor_sync(0xFFFFFFFFu, a0, o);
            a1 += __shfl_xor_sync(0xFFFFFFFFu, a1, o);
        }
        m0 = fmaxf(m0, a0);
        m1 = fmaxf(m1, a1);
    }
    if (lid == 0) { red[wid * 2] = m0; red[wid * 2 + 1] = m1; }
    __syncthreads();
    if (tid == 0) {
        float M0 = red[0], M1 = red[1];
#pragma unroll
        for (int w = 1; w < 8; w++) { M0 = fmaxf(M0, red[2 * w]); M1 = fmaxf(M1, red[2 * w + 1]); }
        g_pmax[blockIdx.x * 2] = M0;
        g_pmax[blockIdx.x * 2 + 1] = M1;
    }
}

// ===================== K4: final max reduce + Linear(2 -> 1) =====================

__global__ void k4_final(const float* __restrict__ W3, const float* __restrict__ b2,
                         const float* __restrict__ b3, float* __restrict__ out) {
    __shared__ float r[8];
    int tid = threadIdx.x;   // 128
    float m0 = g_pmax[tid * 2], m1 = g_pmax[tid * 2 + 1];
#pragma unroll
    for (int o = 16; o; o >>= 1) {
        m0 = fmaxf(m0, __shfl_xor_sync(0xFFFFFFFFu, m0, o));
        m1 = fmaxf(m1, __shfl_xor_sync(0xFFFFFFFFu, m1, o));
    }
    if ((tid & 31) == 0) { r[(tid >> 5) * 2] = m0; r[(tid >> 5) * 2 + 1] = m1; }
    __syncthreads();
    if (tid == 0) {
        float M0 = r[0], M1 = r[1];
#pragma unroll
        for (int w = 1; w < 4; w++) { M0 = fmaxf(M0, r[2 * w]); M1 = fmaxf(M1, r[2 * w + 1]); }
        M0 += b2[0];
        M1 += b2[1];
        out[0] = fmaf(M0, W3[0], fmaf(M1, W3[1], b3[0]));
    }
}

// ===================== Launch =====================

extern "C" void kernel_launch(void* const* d_in, const int* in_sizes, int n_in,
                              void* d_out, int out_size) {
    const float* x   = (const float*)d_in[0];
    const float* adj = (const float*)d_in[1];
    const float* W1  = (const float*)d_in[2];
    const float* b1  = (const float*)d_in[3];
    const float* W2  = (const float*)d_in[4];
    const float* b2  = (const float*)d_in[5];
    const float* W3  = (const float*)d_in[6];
    const float* b3  = (const float*)d_in[7];
    float* out = (float*)d_out;

    cudaFuncSetAttribute(k1_xw1,   cudaFuncAttributeMaxDynamicSharedMemorySize, 81920);
    cudaFuncSetAttribute(k2_pass1, cudaFuncAttributeMaxDynamicSharedMemorySize, 99328);
    cudaFuncSetAttribute(k3_pass2, cudaFuncAttributeMaxDynamicSharedMemorySize, 131072);

    k1_xw1<<<256, 256, 81920>>>(x, W1);
    k2_pass1<<<NMT * KSPLIT, 256, 99328>>>(adj);
    k2b_combine<<<64, 256>>>(b1, W2);
    k3_pass2<<<128, 256, 131072>>>(adj);
    k4_final<<<1, 128>>>(W3, b2, b3, out);
}

// round 4
// speedup vs baseline: 1.4008x; 1.3803x over previous
#include <cuda_runtime.h>
#include <cuda_bf16.h>
#include <cstdint>

// ===================== helpers =====================

__device__ __forceinline__ uint32_t smem_u32(const void* p) {
    uint32_t a;
    asm("{ .reg .u64 t; cvta.to.shared.u64 t, %1; cvt.u32.u64 %0, t; }" : "=r"(a) : "l"(p));
    return a;
}

#define LDMATRIX_X4(r0, r1, r2, r3, addr) \
    asm volatile("ldmatrix.sync.aligned.m8n8.x4.shared.b16 {%0,%1,%2,%3}, [%4];" \
        : "=r"(r0), "=r"(r1), "=r"(r2), "=r"(r3) : "r"(addr))

#define MMA16816(c, a0, a1, a2, a3, b0, b1) \
    asm volatile("mma.sync.aligned.m16n8k16.row.col.f32.bf16.bf16.f32 " \
        "{%0,%1,%2,%3}, {%4,%5,%6,%7}, {%8,%9}, {%0,%1,%2,%3};" \
        : "+f"((c)[0]), "+f"((c)[1]), "+f"((c)[2]), "+f"((c)[3]) \
        : "r"(a0), "r"(a1), "r"(a2), "r"(a3), "r"(b0), "r"(b1))

// ===================== Problem constants =====================

#define NN      16384
#define NFEAT   256
#define NHID    64
#define KC      64            // K chunk per pipeline step
#define NCHUNK  (NN / KC)     // 256
#define KSPLIT  2
#define NCH_H   (NCHUNK / KSPLIT)  // 128 chunks per CTA
#define MTILE   128
#define NMT     (NN / MTILE)  // 128 M-tiles
#define K3_CTAS 1024

// Scratch (static device globals — allocation-free)
__device__ __align__(16) unsigned char g_Bh[NCHUNK * 8192];   // pre-swizzled bf16 hi tiles [chunk][64n x 64k]
__device__ __align__(16) unsigned char g_Bl[NCHUNK * 8192];   // bf16 lo tiles
__device__ __align__(16) float g_Hpart[KSPLIT * NN * NHID];   // partial pre-activation sums (8MB)
__device__ __align__(16) float g_G[NN * 2];                   // h1 @ W2 (before +b2)
__device__ __align__(16) float g_pmax[K3_CTAS * 2];           // per-CTA column maxes

// ===================== K1: B = x @ W1, split to bf16 hi/lo, pre-swizzled =====================

__global__ __launch_bounds__(256) void k1_xw1(const float* __restrict__ x, const float* __restrict__ W1) {
    extern __shared__ char sm1[];
    float* W1s = (float*)sm1;                        // 65536 B
    unsigned char* bh = (unsigned char*)sm1 + 65536; // 8192 B
    unsigned char* bl = bh + 8192;

    int tid = threadIdx.x, wid = tid >> 5, lid = tid & 31;

    const float4* w4 = (const float4*)W1;
    float4* w4s = (float4*)W1s;
#pragma unroll
    for (int i = 0; i < 16; i++) w4s[tid + i * 256] = w4[tid + i * 256];
    __syncthreads();

    int b = blockIdx.x;   // chunk index; covers global k rows [64b, 64b+64)
    for (int i = 0; i < 8; i++) {
        int kl = wid * 8 + i;                 // local k row 0..63
        long k = (long)b * 64 + kl;
        const float* xr = x + k * 256;
        float a0 = 0.f, a1 = 0.f;             // n = 2*lid, 2*lid+1
#pragma unroll 8
        for (int j = 0; j < 256; j++) {
            float xv = __ldg(xr + j);
            float2 wv = *(const float2*)(W1s + j * 64 + 2 * lid);
            a0 = fmaf(xv, wv.x, a0);
            a1 = fmaf(xv, wv.y, a1);
        }
#pragma unroll
        for (int t = 0; t < 2; t++) {
            float a = t ? a1 : a0;
            int n = 2 * lid + t;
            unsigned off = n * 128 + kl * 2;
            unsigned sw = off ^ ((off >> 3) & 0x70);
            __nv_bfloat16 h = __float2bfloat16(a);
            __nv_bfloat16 l = __float2bfloat16(a - __bfloat162float(h));
            *(__nv_bfloat16*)(bh + sw) = h;
            *(__nv_bfloat16*)(bl + sw) = l;
        }
    }
    __syncthreads();

    int4* gh = (int4*)g_Bh + (size_t)b * 512;
    int4* gl = (int4*)g_Bl + (size_t)b * 512;
    const int4* sh = (const int4*)bh;
    const int4* sl = (const int4*)bl;
#pragma unroll
    for (int i = 0; i < 2; i++) {
        gh[tid + i * 256] = sh[tid + i * 256];
        gl[tid + i * 256] = sl[tid + i * 256];
    }
}

// ===================== K2: pass 1 partial — Hpart[half] = adj[:, Khalf] @ B[Khalf] =====================
// grid 256 (= 128 M-tiles x 2 K-halves), block 256, 2 CTAs/SM.

__global__ __launch_bounds__(256, 2) void k2_pass1(const float* __restrict__ adj) {
    extern __shared__ char sm2raw[];
    uint32_t raw = smem_u32(sm2raw);
    uint32_t pad = (1024u - (raw & 1023u)) & 1023u;
    char* sm = sm2raw + pad;
    uint32_t smb = raw + pad;

    const int BUFSZ = 49152;

    int tid = threadIdx.x, wid = tid >> 5, lane = tid & 31;

    int mt   = blockIdx.x >> 1;        // M-tile 0..127
    int half = blockIdx.x & 1;         // K half
    int rb = mt * MTILE;
    int c0 = half * NCH_H;

    float acc[8][4];
#pragma unroll
    for (int i = 0; i < 8; i++)
#pragma unroll
        for (int j = 0; j < 4; j++) acc[i][j] = 0.f;

    int rloc = lane & 15;
    uint32_t aRow = (uint32_t)((wid * 16 + rloc) * 128);
    uint32_t aHi  = (uint32_t)(lane >> 4);
    uint32_t aRx  = (uint32_t)(rloc & 7);
    int nloc = (lane & 7) + ((lane >> 4) << 3);
    uint32_t bKh = (uint32_t)((lane >> 3) & 1);
    uint32_t bNx = (uint32_t)(lane & 7);
    uint32_t bRow = (uint32_t)(nloc * 128);

    float4 v[8];
    int4 bh0, bh1, bl0, bl1;

    auto issue_loads = [&](int ci) {
#pragma unroll
        for (int q = 0; q < 8; q++) {
            int li = q * 256 + tid;
            int row = li >> 4, qk = li & 15;
            v[q] = __ldg((const float4*)(adj + (long)(rb + row) * NN + (long)ci * KC) + qk);
        }
        const int4* gbh = (const int4*)g_Bh + (size_t)ci * 512;
        const int4* gbl = (const int4*)g_Bl + (size_t)ci * 512;
        bh0 = __ldg(gbh + tid); bh1 = __ldg(gbh + tid + 256);
        bl0 = __ldg(gbl + tid); bl1 = __ldg(gbl + tid + 256);
    };

    auto store_chunk = [&](char* buf) {
#pragma unroll
        for (int q = 0; q < 8; q++) {
            int li = q * 256 + tid;
            int row = li >> 4, qk = li & 15;
            unsigned off = row * 128 + qk * 8;
            unsigned sw = off ^ ((row & 7) << 4);
            uint32_t h01, h23, l01, l23;
            asm("cvt.rn.bf16x2.f32 %0, %1, %2;" : "=r"(h01) : "f"(v[q].y), "f"(v[q].x));
            asm("cvt.rn.bf16x2.f32 %0, %1, %2;" : "=r"(h23) : "f"(v[q].w), "f"(v[q].z));
            float lx = v[q].x - __uint_as_float(h01 << 16);
            float ly = v[q].y - __uint_as_float(h01 & 0xffff0000u);
            float lz = v[q].z - __uint_as_float(h23 << 16);
            float lw = v[q].w - __uint_as_float(h23 & 0xffff0000u);
            asm("cvt.rn.bf16x2.f32 %0, %1, %2;" : "=r"(l01) : "f"(ly), "f"(lx));
            asm("cvt.rn.bf16x2.f32 %0, %1, %2;" : "=r"(l23) : "f"(lw), "f"(lz));
            *(uint2*)(buf + 0     + sw) = make_uint2(h01, h23);
            *(uint2*)(buf + 16384 + sw) = make_uint2(l01, l23);
        }
        ((int4*)(buf + 32768))[tid] = bh0; ((int4*)(buf + 32768))[tid + 256] = bh1;
        ((int4*)(buf + 40960))[tid] = bl0; ((int4*)(buf + 40960))[tid + 256] = bl1;
    };

    auto compute = [&](uint32_t bufaddr) {
        uint32_t AH_ = bufaddr, AL_ = bufaddr + 16384;
        uint32_t BH_ = bufaddr + 32768, BL_ = bufaddr + 40960;
#pragma unroll
        for (int ks = 0; ks < 4; ks++) {
            uint32_t au = ((((uint32_t)(ks * 2)) + aHi) ^ aRx) << 4;
            uint32_t ah[4], al[4];
            LDMATRIX_X4(ah[0], ah[1], ah[2], ah[3], AH_ + aRow + au);
            LDMATRIX_X4(al[0], al[1], al[2], al[3], AL_ + aRow + au);
            uint32_t bu = ((((uint32_t)(ks * 2)) + bKh) ^ bNx) << 4;
#pragma unroll
            for (int ntp = 0; ntp < 4; ntp++) {
                uint32_t bh[4], bl[4];
                LDMATRIX_X4(bh[0], bh[1], bh[2], bh[3], BH_ + bRow + bu + ntp * 2048);
                LDMATRIX_X4(bl[0], bl[1], bl[2], bl[3], BL_ + bRow + bu + ntp * 2048);
                MMA16816(acc[2 * ntp],     ah[0], ah[1], ah[2], ah[3], bh[0], bh[1]);
                MMA16816(acc[2 * ntp],     al[0], al[1], al[2], al[3], bh[0], bh[1]);
                MMA16816(acc[2 * ntp],     ah[0], ah[1], ah[2], ah[3], bl[0], bl[1]);
                MMA16816(acc[2 * ntp + 1], ah[0], ah[1], ah[2], ah[3], bh[2], bh[3]);
                MMA16816(acc[2 * ntp + 1], al[0], al[1], al[2], al[3], bh[2], bh[3]);
                MMA16816(acc[2 * ntp + 1], ah[0], ah[1], ah[2], ah[3], bl[2], bl[3]);
            }
        }
    };

    issue_loads(c0);
    store_chunk(sm);
    __syncthreads();

    for (int it = 0; it < NCH_H - 1; it++) {
        int s = it & 1;
        issue_loads(c0 + it + 1);
        compute(smb + s * BUFSZ);
        store_chunk(sm + (s ^ 1) * BUFSZ);
        __syncthreads();
    }
    compute(smb + ((NCH_H - 1) & 1) * BUFSZ);

    float* hp = g_Hpart + (size_t)half * NN * NHID;
    int r0 = rb + wid * 16 + (lane >> 2);
    int ncol = 2 * (lane & 3);
#pragma unroll
    for (int nt = 0; nt < 8; nt++) {
        *(float2*)(hp + (size_t)r0 * NHID + nt * 8 + ncol)       = make_float2(acc[nt][0], acc[nt][1]);
        *(float2*)(hp + (size_t)(r0 + 8) * NHID + nt * 8 + ncol) = make_float2(acc[nt][2], acc[nt][3]);
    }
}

// ===================== K2b: combine halves, +b1, relu, @W2 -> g_G =====================

__global__ __launch_bounds__(256) void k2b_combine(const float* __restrict__ b1,
                                                   const float* __restrict__ W2) {
    __shared__ float sb1[64];
    __shared__ float sW2[128];
    int tid = threadIdx.x;
    if (tid < 64)  sb1[tid] = b1[tid];
    if (tid >= 128 && tid < 256) sW2[tid - 128] = W2[tid - 128];
    __syncthreads();

    int row = blockIdx.x * 256 + tid;
    const float4* p0 = (const float4*)(g_Hpart) + (size_t)row * 16;
    const float4* p1 = (const float4*)(g_Hpart + (size_t)NN * NHID) + (size_t)row * 16;
    float g0 = 0.f, g1 = 0.f;
#pragma unroll
    for (int i = 0; i < 16; i++) {
        float4 a = __ldg(p0 + i);
        float4 b = __ldg(p1 + i);
        int n = i * 4;
        float h;
        h = fmaxf(a.x + b.x + sb1[n + 0], 0.f); g0 = fmaf(h, sW2[2*n + 0], g0); g1 = fmaf(h, sW2[2*n + 1], g1);
        h = fmaxf(a.y + b.y + sb1[n + 1], 0.f); g0 = fmaf(h, sW2[2*n + 2], g0); g1 = fmaf(h, sW2[2*n + 3], g1);
        h = fmaxf(a.z + b.z + sb1[n + 2], 0.f); g0 = fmaf(h, sW2[2*n + 4], g0); g1 = fmaf(h, sW2[2*n + 5], g1);
        h = fmaxf(a.w + b.w + sb1[n + 3], 0.f); g0 = fmaf(h, sW2[2*n + 6], g0); g1 = fmaf(h, sW2[2*n + 7], g1);
    }
    ((float2*)g_G)[row] = make_float2(g0, g1);
}

// ===================== K3: pass 2 — H2 = adj @ G, per-CTA max =====================
// grid 1024, block 256, NO smem staging. One warp per row pair (r, r+8192):
// the two rows share G loads (G stays L1/L2-resident via __ldg; adj streamed
// with __ldcs evict-first). 4 independent accumulator chains per lane.

__global__ __launch_bounds__(256) void k3_pass2(const float* __restrict__ adj) {
    __shared__ float red[32];
    int tid = threadIdx.x, wid = tid >> 5, lane = tid & 31;

    int row0 = blockIdx.x * 8 + wid;       // 0..8191
    int row1 = row0 + 8192;
    const float4* a0p = (const float4*)(adj + (size_t)row0 * NN);
    const float4* a1p = (const float4*)(adj + (size_t)row1 * NN);
    const float4* g = (const float4*)g_G;  // G as float4[8192] (2 nodes per float4)

    float s00 = 0.f, s01 = 0.f, s10 = 0.f, s11 = 0.f;

#pragma unroll 4
    for (int it = 0; it < 128; it++) {     // 4096 float4 per row / 32 lanes
        int j4 = it * 32 + lane;
        float4 av0 = __ldcs(a0p + j4);
        float4 av1 = __ldcs(a1p + j4);
        float4 ga = __ldg(g + 2 * j4);     // nodes 4j, 4j+1
        float4 gb = __ldg(g + 2 * j4 + 1); // nodes 4j+2, 4j+3
        s00 = fmaf(av0.x, ga.x, s00); s01 = fmaf(av0.x, ga.y, s01);
        s10 = fmaf(av1.x, ga.x, s10); s11 = fmaf(av1.x, ga.y, s11);
        s00 = fmaf(av0.y, ga.z, s00); s01 = fmaf(av0.y, ga.w, s01);
        s10 = fmaf(av1.y, ga.z, s10); s11 = fmaf(av1.y, ga.w, s11);
        s00 = fmaf(av0.z, gb.x, s00); s01 = fmaf(av0.z, gb.y, s01);
        s10 = fmaf(av1.z, gb.x, s10); s11 = fmaf(av1.z, gb.y, s11);
        s00 = fmaf(av0.w, gb.z, s00); s01 = fmaf(av0.w, gb.w, s01);
        s10 = fmaf(av1.w, gb.z, s10); s11 = fmaf(av1.w, gb.w, s11);
    }
#pragma unroll
    for (int o = 16; o; o >>= 1) {
        s00 += __shfl_xor_sync(0xFFFFFFFFu, s00, o);
        s01 += __shfl_xor_sync(0xFFFFFFFFu, s01, o);
        s10 += __shfl_xor_sync(0xFFFFFFFFu, s10, o);
        s11 += __shfl_xor_sync(0xFFFFFFFFu, s11, o);
    }
    if (lane == 0) {
        red[wid * 2]      = fmaxf(s00, s10);
        red[wid * 2 + 1]  = fmaxf(s01, s11);
    }
    __syncthreads();
    if (tid == 0) {
        float M0 = red[0], M1 = red[1];
#pragma unroll
        for (int w = 1; w < 8; w++) { M0 = fmaxf(M0, red[2 * w]); M1 = fmaxf(M1, red[2 * w + 1]); }
        g_pmax[blockIdx.x * 2] = M0;
        g_pmax[blockIdx.x * 2 + 1] = M1;
    }
}

// ===================== K4: final max reduce + Linear(2 -> 1) =====================

__global__ void k4_final(const float* __restrict__ W3, const float* __restrict__ b2,
                         const float* __restrict__ b3, float* __restrict__ out) {
    __shared__ float r[16];
    int tid = threadIdx.x;   // 256
    float m0 = -3.402823466e38f, m1 = -3.402823466e38f;
#pragma unroll
    for (int i = 0; i < K3_CTAS / 256; i++) {
        float2 p = ((const float2*)g_pmax)[i * 256 + tid];
        m0 = fmaxf(m0, p.x);
        m1 = fmaxf(m1, p.y);
    }
#pragma unroll
    for (int o = 16; o; o >>= 1) {
        m0 = fmaxf(m0, __shfl_xor_sync(0xFFFFFFFFu, m0, o));
        m1 = fmaxf(m1, __shfl_xor_sync(0xFFFFFFFFu, m1, o));
    }
    if ((tid & 31) == 0) { r[(tid >> 5) * 2] = m0; r[(tid >> 5) * 2 + 1] = m1; }
    __syncthreads();
    if (tid == 0) {
        float M0 = r[0], M1 = r[1];
#pragma unroll
        for (int w = 1; w < 8; w++) { M0 = fmaxf(M0, r[2 * w]); M1 = fmaxf(M1, r[2 * w + 1]); }
        M0 += b2[0];
        M1 += b2[1];
        out[0] = fmaf(M0, W3[0], fmaf(M1, W3[1], b3[0]));
    }
}

// ===================== Launch =====================

extern "C" void kernel_launch(void* const* d_in, const int* in_sizes, int n_in,
                              void* d_out, int out_size) {
    const float* x   = (const float*)d_in[0];
    const float* adj = (const float*)d_in[1];
    const float* W1  = (const float*)d_in[2];
    const float* b1  = (const float*)d_in[3];
    const float* W2  = (const float*)d_in[4];
    const float* b2  = (const float*)d_in[5];
    const float* W3  = (const float*)d_in[6];
    const float* b3  = (const float*)d_in[7];
    float* out = (float*)d_out;

    cudaFuncSetAttribute(k1_xw1,   cudaFuncAttributeMaxDynamicSharedMemorySize, 81920);
    cudaFuncSetAttribute(k2_pass1, cudaFuncAttributeMaxDynamicSharedMemorySize, 99328);

    k1_xw1<<<256, 256, 81920>>>(x, W1);
    k2_pass1<<<NMT * KSPLIT, 256, 99328>>>(adj);
    k2b_combine<<<64, 256>>>(b1, W2);
    k3_pass2<<<K3_CTAS, 256>>>(adj);
    k4_final<<<1, 256>>>(W3, b2, b3, out);
}

// round 7
// speedup vs baseline: 1.5553x; 1.1103x over previous
#include <cuda_runtime.h>
#include <cuda_bf16.h>
#include <cstdint>

// ===================== helpers =====================

__device__ __forceinline__ uint32_t smem_u32(const void* p) {
    uint32_t a;
    asm("{ .reg .u64 t; cvta.to.shared.u64 t, %1; cvt.u32.u64 %0, t; }" : "=r"(a) : "l"(p));
    return a;
}

#define LDMATRIX_X4(r0, r1, r2, r3, addr) \
    asm volatile("ldmatrix.sync.aligned.m8n8.x4.shared.b16 {%0,%1,%2,%3}, [%4];" \
        : "=r"(r0), "=r"(r1), "=r"(r2), "=r"(r3) : "r"(addr))

#define MMA16816(c, a0, a1, a2, a3, b0, b1) \
    asm volatile("mma.sync.aligned.m16n8k16.row.col.f32.bf16.bf16.f32 " \
        "{%0,%1,%2,%3}, {%4,%5,%6,%7}, {%8,%9}, {%0,%1,%2,%3};" \
        : "+f"((c)[0]), "+f"((c)[1]), "+f"((c)[2]), "+f"((c)[3]) \
        : "r"(a0), "r"(a1), "r"(a2), "r"(a3), "r"(b0), "r"(b1))

// ===================== Problem constants =====================

#define NN      16384
#define NFEAT   256
#define NHID    64
#define KC      64            // K chunk per pipeline step
#define NCHUNK  (NN / KC)     // 256
#define KSPLIT  2
#define NCH_H   (NCHUNK / KSPLIT)  // 128 chunks per CTA
#define MTILE   128
#define NMT     (NN / MTILE)  // 128 M-tiles
#define K3_GRID 1024          // x 4 warps = 4096 row-groups of 4 rows

// Scratch (static device globals — allocation-free)
__device__ __align__(16) unsigned char g_Bh[NCHUNK * 8192];   // pre-swizzled bf16 hi tiles [chunk][64n x 64k]
__device__ __align__(16) unsigned char g_Bl[NCHUNK * 8192];   // bf16 lo tiles
__device__ __align__(16) float g_Hpart[KSPLIT * NN * NHID];   // partial pre-activation sums (8MB)
__device__ __align__(16) float g_G[NN * 2];                   // h1 @ W2 (before +b2)
__device__ __align__(16) float g_pmax[K3_GRID * 4 * 2];       // per-warp column maxes

// ===================== K1: B = x @ W1, split to bf16 hi/lo, pre-swizzled =====================

__global__ __launch_bounds__(256) void k1_xw1(const float* __restrict__ x, const float* __restrict__ W1) {
    extern __shared__ char sm1[];
    float* W1s = (float*)sm1;                        // 65536 B
    unsigned char* bh = (unsigned char*)sm1 + 65536; // 8192 B
    unsigned char* bl = bh + 8192;

    int tid = threadIdx.x, wid = tid >> 5, lid = tid & 31;

    const float4* w4 = (const float4*)W1;
    float4* w4s = (float4*)W1s;
#pragma unroll
    for (int i = 0; i < 16; i++) w4s[tid + i * 256] = w4[tid + i * 256];
    __syncthreads();

    int b = blockIdx.x;   // chunk index; covers global k rows [64b, 64b+64)
    for (int i = 0; i < 8; i++) {
        int kl = wid * 8 + i;                 // local k row 0..63
        long k = (long)b * 64 + kl;
        const float* xr = x + k * 256;
        float a0 = 0.f, a1 = 0.f;             // n = 2*lid, 2*lid+1
#pragma unroll 8
        for (int j = 0; j < 256; j++) {
            float xv = __ldg(xr + j);
            float2 wv = *(const float2*)(W1s + j * 64 + 2 * lid);
            a0 = fmaf(xv, wv.x, a0);
            a1 = fmaf(xv, wv.y, a1);
        }
#pragma unroll
        for (int t = 0; t < 2; t++) {
            float a = t ? a1 : a0;
            int n = 2 * lid + t;
            unsigned off = n * 128 + kl * 2;
            unsigned sw = off ^ ((off >> 3) & 0x70);
            __nv_bfloat16 h = __float2bfloat16(a);
            __nv_bfloat16 l = __float2bfloat16(a - __bfloat162float(h));
            *(__nv_bfloat16*)(bh + sw) = h;
            *(__nv_bfloat16*)(bl + sw) = l;
        }
    }
    __syncthreads();

    int4* gh = (int4*)g_Bh + (size_t)b * 512;
    int4* gl = (int4*)g_Bl + (size_t)b * 512;
    const int4* sh = (const int4*)bh;
    const int4* sl = (const int4*)bl;
#pragma unroll
    for (int i = 0; i < 2; i++) {
        gh[tid + i * 256] = sh[tid + i * 256];
        gl[tid + i * 256] = sl[tid + i * 256];
    }
}

// ===================== K2: pass 1 partial — Hpart[half] = adj[:, Khalf] @ B[Khalf] =====================
// grid 256 (= 128 M-tiles x 2 K-halves), block 256, 2 CTAs/SM.
// bf16 hi/lo Markidis 3-term (Ah*Bh + Al*Bh + Ah*Bl), fp32 register accumulators.

__global__ __launch_bounds__(256, 2) void k2_pass1(const float* __restrict__ adj) {
    extern __shared__ char sm2raw[];
    uint32_t raw = smem_u32(sm2raw);
    uint32_t pad = (1024u - (raw & 1023u)) & 1023u;
    char* sm = sm2raw + pad;
    uint32_t smb = raw + pad;

    const int BUFSZ = 49152;

    int tid = threadIdx.x, wid = tid >> 5, lane = tid & 31;

    int mt   = blockIdx.x >> 1;        // M-tile 0..127
    int half = blockIdx.x & 1;         // K half
    int rb = mt * MTILE;
    int c0 = half * NCH_H;

    float acc[8][4];
#pragma unroll
    for (int i = 0; i < 8; i++)
#pragma unroll
        for (int j = 0; j < 4; j++) acc[i][j] = 0.f;

    int rloc = lane & 15;
    uint32_t aRow = (uint32_t)((wid * 16 + rloc) * 128);
    uint32_t aHi  = (uint32_t)(lane >> 4);
    uint32_t aRx  = (uint32_t)(rloc & 7);
    int nloc = (lane & 7) + ((lane >> 4) << 3);
    uint32_t bKh = (uint32_t)((lane >> 3) & 1);
    uint32_t bNx = (uint32_t)(lane & 7);
    uint32_t bRow = (uint32_t)(nloc * 128);

    float4 v[8];
    int4 bh0, bh1, bl0, bl1;

    auto issue_loads = [&](int ci) {
#pragma unroll
        for (int q = 0; q < 8; q++) {
            int li = q * 256 + tid;
            int row = li >> 4, qk = li & 15;
            v[q] = __ldg((const float4*)(adj + (long)(rb + row) * NN + (long)ci * KC) + qk);
        }
        const int4* gbh = (const int4*)g_Bh + (size_t)ci * 512;
        const int4* gbl = (const int4*)g_Bl + (size_t)ci * 512;
        bh0 = __ldg(gbh + tid); bh1 = __ldg(gbh + tid + 256);
        bl0 = __ldg(gbl + tid); bl1 = __ldg(gbl + tid + 256);
    };

    auto store_chunk = [&](char* buf) {
#pragma unroll
        for (int q = 0; q < 8; q++) {
            int li = q * 256 + tid;
            int row = li >> 4, qk = li & 15;
            unsigned off = row * 128 + qk * 8;
            unsigned sw = off ^ ((row & 7) << 4);
            uint32_t h01, h23, l01, l23;
            asm("cvt.rn.bf16x2.f32 %0, %1, %2;" : "=r"(h01) : "f"(v[q].y), "f"(v[q].x));
            asm("cvt.rn.bf16x2.f32 %0, %1, %2;" : "=r"(h23) : "f"(v[q].w), "f"(v[q].z));
            float lx = v[q].x - __uint_as_float(h01 << 16);
            float ly = v[q].y - __uint_as_float(h01 & 0xffff0000u);
            float lz = v[q].z - __uint_as_float(h23 << 16);
            float lw = v[q].w - __uint_as_float(h23 & 0xffff0000u);
            asm("cvt.rn.bf16x2.f32 %0, %1, %2;" : "=r"(l01) : "f"(ly), "f"(lx));
            asm("cvt.rn.bf16x2.f32 %0, %1, %2;" : "=r"(l23) : "f"(lw), "f"(lz));
            *(uint2*)(buf + 0     + sw) = make_uint2(h01, h23);
            *(uint2*)(buf + 16384 + sw) = make_uint2(l01, l23);
        }
        ((int4*)(buf + 32768))[tid] = bh0; ((int4*)(buf + 32768))[tid + 256] = bh1;
        ((int4*)(buf + 40960))[tid] = bl0; ((int4*)(buf + 40960))[tid + 256] = bl1;
    };

    auto compute = [&](uint32_t bufaddr) {
        uint32_t AH_ = bufaddr, AL_ = bufaddr + 16384;
        uint32_t BH_ = bufaddr + 32768, BL_ = bufaddr + 40960;
#pragma unroll
        for (int ks = 0; ks < 4; ks++) {
            uint32_t au = ((((uint32_t)(ks * 2)) + aHi) ^ aRx) << 4;
            uint32_t ah[4], al[4];
            LDMATRIX_X4(ah[0], ah[1], ah[2], ah[3], AH_ + aRow + au);
            LDMATRIX_X4(al[0], al[1], al[2], al[3], AL_ + aRow + au);
            uint32_t bu = ((((uint32_t)(ks * 2)) + bKh) ^ bNx) << 4;
#pragma unroll
            for (int ntp = 0; ntp < 4; ntp++) {
                uint32_t bh[4], bl[4];
                LDMATRIX_X4(bh[0], bh[1], bh[2], bh[3], BH_ + bRow + bu + ntp * 2048);
                LDMATRIX_X4(bl[0], bl[1], bl[2], bl[3], BL_ + bRow + bu + ntp * 2048);
                MMA16816(acc[2 * ntp],     ah[0], ah[1], ah[2], ah[3], bh[0], bh[1]);
                MMA16816(acc[2 * ntp],     al[0], al[1], al[2], al[3], bh[0], bh[1]);
                MMA16816(acc[2 * ntp],     ah[0], ah[1], ah[2], ah[3], bl[0], bl[1]);
                MMA16816(acc[2 * ntp + 1], ah[0], ah[1], ah[2], ah[3], bh[2], bh[3]);
                MMA16816(acc[2 * ntp + 1], al[0], al[1], al[2], al[3], bh[2], bh[3]);
                MMA16816(acc[2 * ntp + 1], ah[0], ah[1], ah[2], ah[3], bl[2], bl[3]);
            }
        }
    };

    issue_loads(c0);
    store_chunk(sm);
    __syncthreads();

    for (int it = 0; it < NCH_H - 1; it++) {
        int s = it & 1;
        issue_loads(c0 + it + 1);
        compute(smb + s * BUFSZ);
        store_chunk(sm + (s ^ 1) * BUFSZ);
        __syncthreads();
    }
    compute(smb + ((NCH_H - 1) & 1) * BUFSZ);

    float* hp = g_Hpart + (size_t)half * NN * NHID;
    int r0 = rb + wid * 16 + (lane >> 2);
    int ncol = 2 * (lane & 3);
#pragma unroll
    for (int nt = 0; nt < 8; nt++) {
        *(float2*)(hp + (size_t)r0 * NHID + nt * 8 + ncol)       = make_float2(acc[nt][0], acc[nt][1]);
        *(float2*)(hp + (size_t)(r0 + 8) * NHID + nt * 8 + ncol) = make_float2(acc[nt][2], acc[nt][3]);
    }
}

// ===================== K2b: combine halves, +b1, relu, @W2 -> g_G =====================

__global__ __launch_bounds__(256) void k2b_combine(const float* __restrict__ b1,
                                                   const float* __restrict__ W2) {
    __shared__ float sb1[64];
    __shared__ float sW2[128];
    int tid = threadIdx.x;
    if (tid < 64)  sb1[tid] = b1[tid];
    if (tid >= 128 && tid < 256) sW2[tid - 128] = W2[tid - 128];
    __syncthreads();

    int row = blockIdx.x * 256 + tid;
    const float4* p0 = (const float4*)(g_Hpart) + (size_t)row * 16;
    const float4* p1 = (const float4*)(g_Hpart + (size_t)NN * NHID) + (size_t)row * 16;
    float g0 = 0.f, g1 = 0.f;
#pragma unroll
    for (int i = 0; i < 16; i++) {
        float4 a = __ldg(p0 + i);
        float4 b = __ldg(p1 + i);
        int n = i * 4;
        float h;
        h = fmaxf(a.x + b.x + sb1[n + 0], 0.f); g0 = fmaf(h, sW2[2*n + 0], g0); g1 = fmaf(h, sW2[2*n + 1], g1);
        h = fmaxf(a.y + b.y + sb1[n + 1], 0.f); g0 = fmaf(h, sW2[2*n + 2], g0); g1 = fmaf(h, sW2[2*n + 3], g1);
        h = fmaxf(a.z + b.z + sb1[n + 2], 0.f); g0 = fmaf(h, sW2[2*n + 4], g0); g1 = fmaf(h, sW2[2*n + 5], g1);
        h = fmaxf(a.w + b.w + sb1[n + 3], 0.f); g0 = fmaf(h, sW2[2*n + 6], g0); g1 = fmaf(h, sW2[2*n + 7], g1);
    }
    ((float2*)g_G)[row] = make_float2(g0, g1);
}

// ===================== K3: pass 2 — H2 = adj @ G, per-warp max =====================
// grid 1024, block 128. Each warp: 4 rows (r, r+4096, r+8192, r+12288) sharing G loads.
// Explicit next-iteration prefetch registers for MLP; adj streamed evict-first.

__global__ __launch_bounds__(128) void k3_pass2(const float* __restrict__ adj) {
    int tid = threadIdx.x, wid = tid >> 5, lane = tid & 31;
    int grp = blockIdx.x * 4 + wid;               // 0..4095

    const float4* a0p = (const float4*)(adj + (size_t)grp * NN);
    const float4* a1p = (const float4*)(adj + (size_t)(grp + 4096) * NN);
    const float4* a2p = (const float4*)(adj + (size_t)(grp + 8192) * NN);
    const float4* a3p = (const float4*)(adj + (size_t)(grp + 12288) * NN);
    const float4* g4 = (const float4*)g_G;

    float s00 = 0.f, s01 = 0.f, s10 = 0.f, s11 = 0.f;
    float s20 = 0.f, s21 = 0.f, s30 = 0.f, s31 = 0.f;

    float4 A0 = __ldcs(a0p + lane);
    float4 A1 = __ldcs(a1p + lane);
    float4 A2 = __ldcs(a2p + lane);
    float4 A3 = __ldcs(a3p + lane);
    float4 G0 = __ldg(g4 + 2 * lane);
    float4 G1 = __ldg(g4 + 2 * lane + 1);

#define K3_FMA() do { \
        s00 = fmaf(A0.x, G0.x, s00); s01 = fmaf(A0.x, G0.y, s01); \
        s10 = fmaf(A1.x, G0.x, s10); s11 = fmaf(A1.x, G0.y, s11); \
        s20 = fmaf(A2.x, G0.x, s20); s21 = fmaf(A2.x, G0.y, s21); \
        s30 = fmaf(A3.x, G0.x, s30); s31 = fmaf(A3.x, G0.y, s31); \
        s00 = fmaf(A0.y, G0.z, s00); s01 = fmaf(A0.y, G0.w, s01); \
        s10 = fmaf(A1.y, G0.z, s10); s11 = fmaf(A1.y, G0.w, s11); \
        s20 = fmaf(A2.y, G0.z, s20); s21 = fmaf(A2.y, G0.w, s21); \
        s30 = fmaf(A3.y, G0.z, s30); s31 = fmaf(A3.y, G0.w, s31); \
        s00 = fmaf(A0.z, G1.x, s00); s01 = fmaf(A0.z, G1.y, s01); \
        s10 = fmaf(A1.z, G1.x, s10); s11 = fmaf(A1.z, G1.y, s11); \
        s20 = fmaf(A2.z, G1.x, s20); s21 = fmaf(A2.z, G1.y, s21); \
        s30 = fmaf(A3.z, G1.x, s30); s31 = fmaf(A3.z, G1.y, s31); \
        s00 = fmaf(A0.w, G1.z, s00); s01 = fmaf(A0.w, G1.w, s01); \
        s10 = fmaf(A1.w, G1.z, s10); s11 = fmaf(A1.w, G1.w, s11); \
        s20 = fmaf(A2.w, G1.z, s20); s21 = fmaf(A2.w, G1.w, s21); \
        s30 = fmaf(A3.w, G1.z, s30); s31 = fmaf(A3.w, G1.w, s31); \
    } while (0)

    for (int it = 1; it < 128; it++) {
        int j4 = it * 32 + lane;
        float4 nA0 = __ldcs(a0p + j4);
        float4 nA1 = __ldcs(a1p + j4);
        float4 nA2 = __ldcs(a2p + j4);
        float4 nA3 = __ldcs(a3p + j4);
        float4 nG0 = __ldg(g4 + 2 * j4);
        float4 nG1 = __ldg(g4 + 2 * j4 + 1);
        K3_FMA();
        A0 = nA0; A1 = nA1; A2 = nA2; A3 = nA3; G0 = nG0; G1 = nG1;
    }
    K3_FMA();
#undef K3_FMA

#pragma unroll
    for (int o = 16; o; o >>= 1) {
        s00 += __shfl_xor_sync(0xFFFFFFFFu, s00, o);
        s01 += __shfl_xor_sync(0xFFFFFFFFu, s01, o);
        s10 += __shfl_xor_sync(0xFFFFFFFFu, s10, o);
        s11 += __shfl_xor_sync(0xFFFFFFFFu, s11, o);
        s20 += __shfl_xor_sync(0xFFFFFFFFu, s20, o);
        s21 += __shfl_xor_sync(0xFFFFFFFFu, s21, o);
        s30 += __shfl_xor_sync(0xFFFFFFFFu, s30, o);
        s31 += __shfl_xor_sync(0xFFFFFFFFu, s31, o);
    }
    if (lane == 0) {
        float m0 = fmaxf(fmaxf(s00, s10), fmaxf(s20, s30));
        float m1 = fmaxf(fmaxf(s01, s11), fmaxf(s21, s31));
        g_pmax[grp * 2]     = m0;
        g_pmax[grp * 2 + 1] = m1;
    }
}

// ===================== K4: final max reduce + Linear(2 -> 1) =====================

__global__ void k4_final(const float* __restrict__ W3, const float* __restrict__ b2,
                         const float* __restrict__ b3, float* __restrict__ out) {
    __shared__ float r[16];
    int tid = threadIdx.x;   // 256
    float m0 = -3.402823466e38f, m1 = -3.402823466e38f;
#pragma unroll
    for (int i = 0; i < (K3_GRID * 4) / 256; i++) {
        float2 p = ((const float2*)g_pmax)[i * 256 + tid];
        m0 = fmaxf(m0, p.x);
        m1 = fmaxf(m1, p.y);
    }
#pragma unroll
    for (int o = 16; o; o >>= 1) {
        m0 = fmaxf(m0, __shfl_xor_sync(0xFFFFFFFFu, m0, o));
        m1 = fmaxf(m1, __shfl_xor_sync(0xFFFFFFFFu, m1, o));
    }
    if ((tid & 31) == 0) { r[(tid >> 5) * 2] = m0; r[(tid >> 5) * 2 + 1] = m1; }
    __syncthreads();
    if (tid == 0) {
        float M0 = r[0], M1 = r[1];
#pragma unroll
        for (int w = 1; w < 8; w++) { M0 = fmaxf(M0, r[2 * w]); M1 = fmaxf(M1, r[2 * w + 1]); }
        M0 += b2[0];
        M1 += b2[1];
        out[0] = fmaf(M0, W3[0], fmaf(M1, W3[1], b3[0]));
    }
}

// ===================== Launch =====================

extern "C" void kernel_launch(void* const* d_in, const int* in_sizes, int n_in,
                              void* d_out, int out_size) {
    const float* x   = (const float*)d_in[0];
    const float* adj = (const float*)d_in[1];
    const float* W1  = (const float*)d_in[2];
    const float* b1  = (const float*)d_in[3];
    const float* W2  = (const float*)d_in[4];
    const float* b2  = (const float*)d_in[5];
    const float* W3  = (const float*)d_in[6];
    const float* b3  = (const float*)d_in[7];
    float* out = (float*)d_out;

    cudaFuncSetAttribute(k1_xw1,   cudaFuncAttributeMaxDynamicSharedMemorySize, 81920);
    cudaFuncSetAttribute(k2_pass1, cudaFuncAttributeMaxDynamicSharedMemorySize, 99328);

    k1_xw1<<<256, 256, 81920>>>(x, W1);
    k2_pass1<<<NMT * KSPLIT, 256, 99328>>>(adj);
    k2b_combine<<<64, 256>>>(b1, W2);
    k3_pass2<<<K3_GRID, 128>>>(adj);
    k4_final<<<1, 256>>>(W3, b2, b3, out);
}